// round 12
// baseline (speedup 1.0000x reference)
#include <cuda_runtime.h>
#include <cuda_fp16.h>
#include <stdint.h>

#define B  4096
#define T  28
#define H  128
#define F0 28
#define NL 10
#define NC 10
#define BT 32           // batch rows per CTA (two m16 tiles)
#define CTAS (B / BT)   // 128 -> single wave on 148 SMs
#define NT 512          // 16 warps: 0-7 scan, 8-15 projection

// Static device buffers (no allocation allowed). xp ping-pong, fragment order.
__device__ float g_xpA[(size_t)B * T * H];
__device__ float g_xpB[(size_t)B * T * H];

// ---------------------------------------------------------------------------
// helpers
// ---------------------------------------------------------------------------
__device__ __forceinline__ uint32_t cvt_pack(float lo, float hi) {
    uint32_t r; asm("cvt.rn.f16x2.f32 %0, %1, %2;" : "=r"(r) : "f"(hi), "f"(lo));
    return r;
}
__device__ __forceinline__ float tanh32(float x) {
    float r; asm("tanh.approx.f32 %0, %1;" : "=f"(r) : "f"(x));
    return r;
}
__device__ __forceinline__ void mma16(float c[4], uint4 a, const uint32_t b[2]) {
    asm volatile("mma.sync.aligned.m16n8k16.row.col.f32.f16.f16.f32 "
        "{%0,%1,%2,%3}, {%4,%5,%6,%7}, {%8,%9}, {%0,%1,%2,%3};"
        : "+f"(c[0]), "+f"(c[1]), "+f"(c[2]), "+f"(c[3])
        : "r"(a.x), "r"(a.y), "r"(a.z), "r"(a.w), "r"(b[0]), "r"(b[1]));
}
// A-fragment word index for element (rl 0..15, kk 0..15) of one m16k16 tile
__device__ __forceinline__ int awidx(int rl, int kk) {
    int lane = ((rl & 7) << 2) | ((kk & 7) >> 1);
    int reg  = ((kk & 8) >> 2) | (rl >> 3);
    return lane * 4 + reg;               // half select = kk & 1
}

// ---------------------------------------------------------------------------
// Persistent whole-network kernel. Warp (role, m2, nq): each warp owns ONE
// m16 tile and 32 n-columns -> loads only its m-tile's h fragments (halved
// SMEM crossbar traffic vs 2-m-tile warps).
//   scan warps (0-7):  h_t = tanh(xp_l[t] + h_{t-1} @ Whh_l^T)
//   proj warps (8-15): xp_{l+1}[t-1] = h_{t-1} @ Wih_{l+1}^T + b_{l+1}
// ---------------------------------------------------------------------------
__global__ void __launch_bounds__(NT, 1)
rnn_net(const float* __restrict__ x,      // [B, T, F0]
        const float* __restrict__ Wih0,   // [H, F0]
        const float* __restrict__ WihR,   // [NL-1, H, H]
        const float* __restrict__ Whh,    // [NL, H, H]
        const float* __restrict__ bih,    // [NL, H]
        const float* __restrict__ bhh,    // [NL, H]
        const float* __restrict__ fcW,    // [NC, H]
        const float* __restrict__ fcb,    // [NC]
        float*       __restrict__ out,    // [B, NC]
        float*       __restrict__ xpA,
        float*       __restrict__ xpB)
{
    // h fragments: [buf][m2][kc][lane*4+reg]  (2*2*1024 words)
    __shared__ __align__(16) uint32_t AsH[4096];
    __shared__ float hsm[BT][H];

    const int tid  = threadIdx.x;
    const int lane = tid & 31;
    const int w    = tid >> 5;
    const bool scanw = (w < 8);
    const int sw   = w & 7;
    const int m2   = sw >> 2;            // which m16 tile this warp owns
    const int nq   = sw & 3;             // 32-column slice [32nq, 32nq+32)
    const int grp  = lane >> 2;
    const int tig  = lane & 3;
    const int b0   = blockIdx.x * BT;
    const size_t cta_off = (size_t)blockIdx.x * (T * 4096);
    float* xp0 = xpA + cta_off;
    float* xp1 = xpB + cta_off;

    // xp element base for this warp's (m2, nq) block at timestep t:
    //   t*4096 + m2*2048 + nq*512 + nt*128 + lane*4
    // =======================================================================
    // PHASE A: xp0 = x @ Wih0^T + b_0.
    // 16 warps = 2 timesteps (tt = w>>3) x 8 slots (m2, nq).
    // =======================================================================
    {
        const int tt = w >> 3;
        uint32_t Phi[2][4][2];
#pragma unroll
        for (int kc = 0; kc < 2; ++kc)
#pragma unroll
            for (int nt = 0; nt < 4; ++nt) {
                int n  = nq * 32 + nt * 8 + grp;
                int k0 = kc * 16 + 2 * tig;
                float v00 = (k0     < F0) ? Wih0[n * F0 + k0]     : 0.0f;
                float v01 = (k0 + 1 < F0) ? Wih0[n * F0 + k0 + 1] : 0.0f;
                float v10 = (k0 + 8 < F0) ? Wih0[n * F0 + k0 + 8] : 0.0f;
                float v11 = (k0 + 9 < F0) ? Wih0[n * F0 + k0 + 9] : 0.0f;
                Phi[kc][nt][0] = cvt_pack(v00, v01);
                Phi[kc][nt][1] = cvt_pack(v10, v11);
            }
        float bi0[4][2];
#pragma unroll
        for (int nt = 0; nt < 4; ++nt) {
            int c0 = nq * 32 + nt * 8 + 2 * tig;
            bi0[nt][0] = bih[c0]     + bhh[c0];
            bi0[nt][1] = bih[c0 + 1] + bhh[c0 + 1];
        }

        __half* AsHh = reinterpret_cast<__half*>(AsH);
        for (int tp = 0; tp < T; tp += 2) {
            // stage TWO timesteps: word = tt*2048 + m2*1024 + kc*128 + awidx
            for (int i = tid; i < 2048; i += NT) {
                int ts = i >> 10, r = (i >> 5) & 31, k = i & 31;
                float v = (k < F0)
                    ? x[((size_t)(b0 + r) * T + (tp + ts)) * F0 + k] : 0.0f;
                int word = ts * 2048 + (r >> 4) * 1024 + (k >> 4) * 128 + awidx(r & 15, k & 15);
                AsHh[2 * word + (k & 1)] = __float2half_rn(v);
            }
            __syncthreads();
            {
                float acc[4][4];
#pragma unroll
                for (int nt = 0; nt < 4; ++nt)
#pragma unroll
                    for (int j = 0; j < 4; ++j) acc[nt][j] = bi0[nt][j & 1];
#pragma unroll
                for (int kc = 0; kc < 2; ++kc) {
                    uint4 a = *(const uint4*)&AsH[tt * 2048 + m2 * 1024 + kc * 128 + lane * 4];
#pragma unroll
                    for (int nt = 0; nt < 4; ++nt)
                        mma16(acc[nt], a, Phi[kc][nt]);
                }
                float* db = xp0 + (size_t)(tp + tt) * 4096 + m2 * 2048 + nq * 512 + lane * 4;
#pragma unroll
                for (int nt = 0; nt < 4; ++nt)
                    *(float4*)(db + nt * 128) =
                        make_float4(acc[nt][0], acc[nt][1], acc[nt][2], acc[nt][3]);
            }
            __syncthreads();
        }
    }

    // =======================================================================
    // MAIN: 10 fused scan+projection layers
    // =======================================================================
    uint32_t Bw[8][4][2];   // role weight fragments (fp16), 64 regs
    float bP[4][2];         // proj bias (layer l+1)

    for (int l = 0; l < NL; ++l) {
        const float* xin  = (l & 1) ? xp1 : xp0;
        float*       xout = (l & 1) ? xp0 : xp1;

        {
            const float* Wsel = scanw ? (Whh + (size_t)l * H * H)
                                      : (l < NL - 1 ? WihR + (size_t)l * H * H : nullptr);
            if (Wsel) {
#pragma unroll
                for (int kc = 0; kc < 8; ++kc)
#pragma unroll
                    for (int nt = 0; nt < 4; ++nt) {
                        int n  = nq * 32 + nt * 8 + grp;
                        int k0 = kc * 16 + 2 * tig;
                        Bw[kc][nt][0] = cvt_pack(Wsel[n * H + k0],     Wsel[n * H + k0 + 1]);
                        Bw[kc][nt][1] = cvt_pack(Wsel[n * H + k0 + 8], Wsel[n * H + k0 + 9]);
                    }
            }
            if (!scanw && l < NL - 1) {
                const float* bi = bih + (size_t)(l + 1) * H;
                const float* bh = bhh + (size_t)(l + 1) * H;
#pragma unroll
                for (int nt = 0; nt < 4; ++nt) {
                    int c0 = nq * 32 + nt * 8 + 2 * tig;
                    bP[nt][0] = bi[c0]     + bh[c0];
                    bP[nt][1] = bi[c0 + 1] + bh[c0 + 1];
                }
            }
        }

        // zero h buffer 0 (h_{-1} = 0)
        for (int i = tid; i < 2048; i += NT) AsH[i] = 0u;
        __syncthreads();

        int p = 0;
        float4 xv[4];
        if (scanw) {
            const float* sb = xin + m2 * 2048 + nq * 512 + lane * 4;
#pragma unroll
            for (int nt = 0; nt < 4; ++nt) xv[nt] = *(const float4*)(sb + nt * 128);
        }

        for (int t = 0; t < T; ++t) {
            if (scanw) {
                // ---- scan: h_t = tanh(xp[t] + h_{t-1} @ Whh^T) ----
                float acc[4][4];
#pragma unroll
                for (int nt = 0; nt < 4; ++nt) {
                    acc[nt][0] = xv[nt].x; acc[nt][1] = xv[nt].y;
                    acc[nt][2] = xv[nt].z; acc[nt][3] = xv[nt].w;
                }
                if (t + 1 < T) {
                    const float* nb = xin + (size_t)(t + 1) * 4096 + m2 * 2048 + nq * 512 + lane * 4;
#pragma unroll
                    for (int nt = 0; nt < 4; ++nt) xv[nt] = *(const float4*)(nb + nt * 128);
                }
#pragma unroll
                for (int kc = 0; kc < 8; ++kc) {
                    uint4 a = *(const uint4*)&AsH[p * 2048 + m2 * 1024 + kc * 128 + lane * 4];
#pragma unroll
                    for (int nt = 0; nt < 4; ++nt)
                        mma16(acc[nt], a, Bw[kc][nt]);
                }
                float y[4][4];
#pragma unroll
                for (int nt = 0; nt < 4; ++nt)
#pragma unroll
                    for (int j = 0; j < 4; ++j) y[nt][j] = tanh32(acc[nt][j]);

                // nt pair (0,1) -> kc = 2nq ; nt pair (2,3) -> kc = 2nq+1
                uint4 hv0, hv1;
                hv0.x = cvt_pack(y[0][0], y[0][1]); hv0.y = cvt_pack(y[0][2], y[0][3]);
                hv0.z = cvt_pack(y[1][0], y[1][1]); hv0.w = cvt_pack(y[1][2], y[1][3]);
                hv1.x = cvt_pack(y[2][0], y[2][1]); hv1.y = cvt_pack(y[2][2], y[2][3]);
                hv1.z = cvt_pack(y[3][0], y[3][1]); hv1.w = cvt_pack(y[3][2], y[3][3]);
                *(uint4*)&AsH[(1 - p) * 2048 + m2 * 1024 + (2 * nq)     * 128 + lane * 4] = hv0;
                *(uint4*)&AsH[(1 - p) * 2048 + m2 * 1024 + (2 * nq + 1) * 128 + lane * 4] = hv1;

                if (l == NL - 1 && t == T - 1) {
#pragma unroll
                    for (int nt = 0; nt < 4; ++nt) {
                        int c0 = nq * 32 + nt * 8 + 2 * tig;
                        hsm[m2 * 16 + grp][c0]         = y[nt][0];
                        hsm[m2 * 16 + grp][c0 + 1]     = y[nt][1];
                        hsm[m2 * 16 + grp + 8][c0]     = y[nt][2];
                        hsm[m2 * 16 + grp + 8][c0 + 1] = y[nt][3];
                    }
                }
            } else if (l < NL - 1 && t > 0) {
                // ---- proj: xp_{l+1}[t-1] = h_{t-1} @ Wih_{l+1}^T + b ----
                float acc[4][4];
#pragma unroll
                for (int nt = 0; nt < 4; ++nt)
#pragma unroll
                    for (int j = 0; j < 4; ++j) acc[nt][j] = bP[nt][j & 1];
#pragma unroll
                for (int kc = 0; kc < 8; ++kc) {
                    uint4 a = *(const uint4*)&AsH[p * 2048 + m2 * 1024 + kc * 128 + lane * 4];
#pragma unroll
                    for (int nt = 0; nt < 4; ++nt)
                        mma16(acc[nt], a, Bw[kc][nt]);
                }
                float* db = xout + (size_t)(t - 1) * 4096 + m2 * 2048 + nq * 512 + lane * 4;
#pragma unroll
                for (int nt = 0; nt < 4; ++nt)
                    *(float4*)(db + nt * 128) =
                        make_float4(acc[nt][0], acc[nt][1], acc[nt][2], acc[nt][3]);
            }
            __syncthreads();
            p ^= 1;
        }

        // tail: project h_{T-1} (in buf p)
        if (!scanw && l < NL - 1) {
            float acc[4][4];
#pragma unroll
            for (int nt = 0; nt < 4; ++nt)
#pragma unroll
                for (int j = 0; j < 4; ++j) acc[nt][j] = bP[nt][j & 1];
#pragma unroll
            for (int kc = 0; kc < 8; ++kc) {
                uint4 a = *(const uint4*)&AsH[p * 2048 + m2 * 1024 + kc * 128 + lane * 4];
#pragma unroll
                for (int nt = 0; nt < 4; ++nt)
                    mma16(acc[nt], a, Bw[kc][nt]);
            }
            float* db = xout + (size_t)(T - 1) * 4096 + m2 * 2048 + nq * 512 + lane * 4;
#pragma unroll
            for (int nt = 0; nt < 4; ++nt)
                *(float4*)(db + nt * 128) =
                    make_float4(acc[nt][0], acc[nt][1], acc[nt][2], acc[nt][3]);
        }
        __syncthreads();
    }

    // =======================================================================
    // FC head
    // =======================================================================
    if (tid < BT * NC) {
        int r = tid / NC, c = tid - r * NC;
        const float* wgt = fcW + c * H;
        float s = fcb[c];
#pragma unroll 8
        for (int k = 0; k < H; ++k) s += hsm[r][k] * wgt[k];
        out[(size_t)(b0 + r) * NC + c] = s;
    }
}

extern "C" void kernel_launch(void* const* d_in, const int* in_sizes, int n_in,
                              void* d_out, int out_size)
{
    const float* x    = (const float*)d_in[0];
    const float* Wih0 = (const float*)d_in[1];
    const float* Wih  = (const float*)d_in[2];
    const float* Whh  = (const float*)d_in[3];
    const float* bih  = (const float*)d_in[4];
    const float* bhh  = (const float*)d_in[5];
    const float* fcW  = (const float*)d_in[6];
    const float* fcb  = (const float*)d_in[7];
    float* out = (float*)d_out;

    float *xpA, *xpB;
    cudaGetSymbolAddress((void**)&xpA, g_xpA);
    cudaGetSymbolAddress((void**)&xpB, g_xpB);

    rnn_net<<<CTAS, NT>>>(x, Wih0, Wih, Whh, bih, bhh, fcW, fcb, out, xpA, xpB);
}

// round 13
// speedup vs baseline: 1.1163x; 1.1163x over previous
#include <cuda_runtime.h>
#include <cuda_fp16.h>
#include <stdint.h>

#define B  4096
#define T  28
#define H  128
#define F0 28
#define NL 10
#define NC 10
#define BT 32           // batch rows per CTA (two m16 tiles)
#define CTAS (B / BT)   // 128 -> single wave on 148 SMs
#define NT 512          // 16 warps: 0-7 scan, 8-15 projection

// Static device buffers (no allocation allowed). xp ping-pong, fragment order.
__device__ float g_xpA[(size_t)B * T * H];
__device__ float g_xpB[(size_t)B * T * H];

// ---------------------------------------------------------------------------
// helpers
// ---------------------------------------------------------------------------
__device__ __forceinline__ uint32_t cvt_pack(float lo, float hi) {
    uint32_t r; asm("cvt.rn.f16x2.f32 %0, %1, %2;" : "=r"(r) : "f"(hi), "f"(lo));
    return r;
}
__device__ __forceinline__ float tanh32(float x) {
    float r; asm("tanh.approx.f32 %0, %1;" : "=f"(r) : "f"(x));
    return r;
}
__device__ __forceinline__ void mma16(float c[4], uint4 a, const uint32_t b[2]) {
    asm volatile("mma.sync.aligned.m16n8k16.row.col.f32.f16.f16.f32 "
        "{%0,%1,%2,%3}, {%4,%5,%6,%7}, {%8,%9}, {%0,%1,%2,%3};"
        : "+f"(c[0]), "+f"(c[1]), "+f"(c[2]), "+f"(c[3])
        : "r"(a.x), "r"(a.y), "r"(a.z), "r"(a.w), "r"(b[0]), "r"(b[1]));
}
// A-fragment word index for element (rl 0..15, kk 0..15) of one m16k16 tile
__device__ __forceinline__ int awidx(int rl, int kk) {
    int lane = ((rl & 7) << 2) | ((kk & 7) >> 1);
    int reg  = ((kk & 8) >> 2) | (rl >> 3);
    return lane * 4 + reg;               // half select = kk & 1
}
// named barriers
__device__ __forceinline__ void bsync(int id, int cnt) {
    asm volatile("bar.sync %0, %1;" :: "r"(id), "r"(cnt) : "memory");
}
__device__ __forceinline__ void barrive(int id, int cnt) {
    asm volatile("bar.arrive %0, %1;" :: "r"(id), "r"(cnt) : "memory");
}

// ---------------------------------------------------------------------------
// Persistent whole-network kernel, warp-specialized with DECOUPLED groups:
//   scan warps (0-7):  h_t = tanh(xp_l[t] + h_{t-1} @ Whh_l^T)
//   proj warps (8-15): xp_{l+1}[j] = h_j @ Wih_{l+1}^T + b_{l+1}
// h lives in a 3-slot SMEM ring; producer/consumer named barriers give proj
// up to 3 steps of slack so its latency is off the scan critical path.
//   slot(h[t]) = (t+1) % 3
//   id 1        : scan-internal barrier (count 256)
//   ids 2+t%3   : h-ready   (scan arrive, proj sync; count 512)
//   ids 5+j%3   : slot-free (proj arrive for j<=T-4, scan sync at t=j+3)
// ---------------------------------------------------------------------------
__global__ void __launch_bounds__(NT, 1)
rnn_net(const float* __restrict__ x,      // [B, T, F0]
        const float* __restrict__ Wih0,   // [H, F0]
        const float* __restrict__ WihR,   // [NL-1, H, H]
        const float* __restrict__ Whh,    // [NL, H, H]
        const float* __restrict__ bih,    // [NL, H]
        const float* __restrict__ bhh,    // [NL, H]
        const float* __restrict__ fcW,    // [NC, H]
        const float* __restrict__ fcb,    // [NC]
        float*       __restrict__ out,    // [B, NC]
        float*       __restrict__ xpA,
        float*       __restrict__ xpB)
{
    // h ring: [slot 0..2][m2][kc][lane*4+reg] = 3 * 2048 words
    __shared__ __align__(16) uint32_t AsH[3 * 2048];
    __shared__ float hsm[BT][H];

    const int tid  = threadIdx.x;
    const int lane = tid & 31;
    const int w    = tid >> 5;
    const bool scanw = (w < 8);
    const int ns   = w & 7;
    const int grp  = lane >> 2;
    const int tig  = lane & 3;
    const int b0   = blockIdx.x * BT;
    const size_t cta_off = (size_t)blockIdx.x * (T * 4096);
    float* xp0 = xpA + cta_off;
    float* xp1 = xpB + cta_off;

    // =======================================================================
    // PHASE A: xp0 = x @ Wih0^T + b_0.  Warp w -> tile (m2 = w>>3, ns).
    // =======================================================================
    {
        const int am2 = w >> 3;
        uint32_t Phi[2][2][2];
#pragma unroll
        for (int kc = 0; kc < 2; ++kc)
#pragma unroll
            for (int nt = 0; nt < 2; ++nt) {
                int n  = ns * 16 + nt * 8 + grp;
                int k0 = kc * 16 + 2 * tig;
                float v00 = (k0     < F0) ? Wih0[n * F0 + k0]     : 0.0f;
                float v01 = (k0 + 1 < F0) ? Wih0[n * F0 + k0 + 1] : 0.0f;
                float v10 = (k0 + 8 < F0) ? Wih0[n * F0 + k0 + 8] : 0.0f;
                float v11 = (k0 + 9 < F0) ? Wih0[n * F0 + k0 + 9] : 0.0f;
                Phi[kc][nt][0] = cvt_pack(v00, v01);
                Phi[kc][nt][1] = cvt_pack(v10, v11);
            }
        float bi0[2][2];
#pragma unroll
        for (int nt = 0; nt < 2; ++nt) {
            int c0 = ns * 16 + nt * 8 + 2 * tig;
            bi0[nt][0] = bih[c0]     + bhh[c0];
            bi0[nt][1] = bih[c0 + 1] + bhh[c0 + 1];
        }

        __half* AsHh = reinterpret_cast<__half*>(AsH);
        for (int t = 0; t < T; ++t) {
            for (int i = tid; i < 1024; i += NT) {
                int r = i >> 5, k = i & 31;
                float v = (k < F0)
                    ? x[((size_t)(b0 + r) * T + t) * F0 + k] : 0.0f;
                int word = (r >> 4) * 1024 + (k >> 4) * 128 + awidx(r & 15, k & 15);
                AsHh[2 * word + (k & 1)] = __float2half_rn(v);
            }
            __syncthreads();
            {
                float acc[2][4];
#pragma unroll
                for (int nt = 0; nt < 2; ++nt)
#pragma unroll
                    for (int j = 0; j < 4; ++j) acc[nt][j] = bi0[nt][j & 1];
#pragma unroll
                for (int kc = 0; kc < 2; ++kc) {
                    uint4 ah = *(const uint4*)&AsH[am2 * 1024 + kc * 128 + lane * 4];
#pragma unroll
                    for (int nt = 0; nt < 2; ++nt)
                        mma16(acc[nt], ah, Phi[kc][nt]);
                }
                float4* dst = (float4*)(xp0 + (size_t)t * 4096 + am2 * 2048 + ns * 256 + lane * 8);
                dst[0] = make_float4(acc[0][0], acc[0][1], acc[0][2], acc[0][3]);
                dst[1] = make_float4(acc[1][0], acc[1][1], acc[1][2], acc[1][3]);
            }
            __syncthreads();
        }
    }

    // =======================================================================
    // MAIN: 10 fused scan+projection layers (decoupled groups)
    // =======================================================================
    uint32_t Bw[8][2][2];   // role weight fragments (fp16)
    float bP[2][2];         // proj bias (layer l+1)

    for (int l = 0; l < NL; ++l) {
        const float* xin  = (l & 1) ? xp1 : xp0;
        float*       xout = (l & 1) ? xp0 : xp1;

        {
            const float* Wsel = scanw ? (Whh + (size_t)l * H * H)
                                      : (l < NL - 1 ? WihR + (size_t)l * H * H : nullptr);
            if (Wsel) {
#pragma unroll
                for (int kc = 0; kc < 8; ++kc)
#pragma unroll
                    for (int nt = 0; nt < 2; ++nt) {
                        int n  = ns * 16 + nt * 8 + grp;
                        int k0 = kc * 16 + 2 * tig;
                        Bw[kc][nt][0] = cvt_pack(Wsel[n * H + k0],     Wsel[n * H + k0 + 1]);
                        Bw[kc][nt][1] = cvt_pack(Wsel[n * H + k0 + 8], Wsel[n * H + k0 + 9]);
                    }
            }
            if (!scanw && l < NL - 1) {
                const float* bi = bih + (size_t)(l + 1) * H;
                const float* bh = bhh + (size_t)(l + 1) * H;
#pragma unroll
                for (int nt = 0; nt < 2; ++nt) {
                    int c0 = ns * 16 + nt * 8 + 2 * tig;
                    bP[nt][0] = bi[c0]     + bh[c0];
                    bP[nt][1] = bi[c0 + 1] + bh[c0 + 1];
                }
            }
        }

        // zero slot 0 (h_{-1} = 0)
        for (int i = tid; i < 2048; i += NT) AsH[i] = 0u;
        __syncthreads();

        if (scanw) {
            // ---------------- SCAN GROUP ----------------
            float4 xv0, xv1;
            {
                const float4* s0 = (const float4*)(xin + ns * 256 + lane * 8);
                const float4* s1 = (const float4*)(xin + 2048 + ns * 256 + lane * 8);
                xv0 = s0[0]; xv1 = s0[1];
                // second m-tile prefetch folded into xv pair loads below
                xv1 = s0[1];
                float4 t0 = s1[0], t1 = s1[1];
                // keep all four in registers:
                // xv0,xv1 = m2=0 ; xw0,xw1 = m2=1
                // (declare here)
                float4 xw0 = t0, xw1 = t1;

                for (int t = 0; t < T; ++t) {
                    const int rslot = t % 3;           // holds h[t-1]
                    const int wslot = (t + 1) % 3;     // will hold h[t]
                    if (t >= 3) bsync(5 + (t % 3), NT);   // slot-free from proj

                    float acc[2][2][4];
                    acc[0][0][0] = xv0.x; acc[0][0][1] = xv0.y; acc[0][0][2] = xv0.z; acc[0][0][3] = xv0.w;
                    acc[0][1][0] = xv1.x; acc[0][1][1] = xv1.y; acc[0][1][2] = xv1.z; acc[0][1][3] = xv1.w;
                    acc[1][0][0] = xw0.x; acc[1][0][1] = xw0.y; acc[1][0][2] = xw0.z; acc[1][0][3] = xw0.w;
                    acc[1][1][0] = xw1.x; acc[1][1][1] = xw1.y; acc[1][1][2] = xw1.z; acc[1][1][3] = xw1.w;
                    if (t + 1 < T) {
                        const float4* n0 = (const float4*)(xin + (size_t)(t + 1) * 4096 + ns * 256 + lane * 8);
                        const float4* n1 = (const float4*)(xin + (size_t)(t + 1) * 4096 + 2048 + ns * 256 + lane * 8);
                        xv0 = n0[0]; xv1 = n0[1]; xw0 = n1[0]; xw1 = n1[1];
                    }
#pragma unroll
                    for (int kc = 0; kc < 8; ++kc) {
                        uint4 a0 = *(const uint4*)&AsH[rslot * 2048 + kc * 128 + lane * 4];
                        uint4 a1 = *(const uint4*)&AsH[rslot * 2048 + 1024 + kc * 128 + lane * 4];
#pragma unroll
                        for (int nt = 0; nt < 2; ++nt) {
                            mma16(acc[0][nt], a0, Bw[kc][nt]);
                            mma16(acc[1][nt], a1, Bw[kc][nt]);
                        }
                    }
#pragma unroll
                    for (int m2 = 0; m2 < 2; ++m2) {
                        float y00 = tanh32(acc[m2][0][0]), y01 = tanh32(acc[m2][0][1]);
                        float y02 = tanh32(acc[m2][0][2]), y03 = tanh32(acc[m2][0][3]);
                        float y10 = tanh32(acc[m2][1][0]), y11 = tanh32(acc[m2][1][1]);
                        float y12 = tanh32(acc[m2][1][2]), y13 = tanh32(acc[m2][1][3]);
                        uint4 hv;
                        hv.x = cvt_pack(y00, y01);
                        hv.y = cvt_pack(y02, y03);
                        hv.z = cvt_pack(y10, y11);
                        hv.w = cvt_pack(y12, y13);
                        *(uint4*)&AsH[wslot * 2048 + m2 * 1024 + ns * 128 + lane * 4] = hv;

                        if (l == NL - 1 && t == T - 1) {
#pragma unroll
                            for (int nt = 0; nt < 2; ++nt) {
                                int c0 = ns * 16 + nt * 8 + 2 * tig;
                                float a  = (nt == 0) ? y00 : y10;
                                float bb = (nt == 0) ? y01 : y11;
                                float cc = (nt == 0) ? y02 : y12;
                                float dd = (nt == 0) ? y03 : y13;
                                hsm[m2 * 16 + grp][c0]         = a;
                                hsm[m2 * 16 + grp][c0 + 1]     = bb;
                                hsm[m2 * 16 + grp + 8][c0]     = cc;
                                hsm[m2 * 16 + grp + 8][c0 + 1] = dd;
                            }
                        }
                    }
                    barrive(2 + (t % 3), NT);      // h[t] ready for proj
                    bsync(1, 256);                 // scan-internal: writes visible
                }
            }
        } else {
            // ---------------- PROJ GROUP ----------------
            for (int j = 0; j < T; ++j) {
                const int slot = (j + 1) % 3;      // holds h[j]
                bsync(2 + (j % 3), NT);            // wait for h[j]
                if (l < NL - 1) {
                    float acc[2][2][4];
#pragma unroll
                    for (int m2 = 0; m2 < 2; ++m2)
#pragma unroll
                        for (int nt = 0; nt < 2; ++nt)
#pragma unroll
                            for (int jj = 0; jj < 4; ++jj) acc[m2][nt][jj] = bP[nt][jj & 1];
#pragma unroll
                    for (int kc = 0; kc < 8; ++kc) {
                        uint4 a0 = *(const uint4*)&AsH[slot * 2048 + kc * 128 + lane * 4];
                        uint4 a1 = *(const uint4*)&AsH[slot * 2048 + 1024 + kc * 128 + lane * 4];
#pragma unroll
                        for (int nt = 0; nt < 2; ++nt) {
                            mma16(acc[0][nt], a0, Bw[kc][nt]);
                            mma16(acc[1][nt], a1, Bw[kc][nt]);
                        }
                    }
#pragma unroll
                    for (int m2 = 0; m2 < 2; ++m2) {
                        float4* dst = (float4*)(xout + (size_t)j * 4096 + m2 * 2048 + ns * 256 + lane * 8);
                        dst[0] = make_float4(acc[m2][0][0], acc[m2][0][1], acc[m2][0][2], acc[m2][0][3]);
                        dst[1] = make_float4(acc[m2][1][0], acc[m2][1][1], acc[m2][1][2], acc[m2][1][3]);
                    }
                }
                if (j <= T - 4) barrive(5 + (j % 3), NT);   // slot free
            }
        }
        __syncthreads();   // layer boundary: orders smem ring + global xp
    }

    // =======================================================================
    // FC head
    // =======================================================================
    if (tid < BT * NC) {
        int r = tid / NC, c = tid - r * NC;
        const float* wgt = fcW + c * H;
        float s = fcb[c];
#pragma unroll 8
        for (int k = 0; k < H; ++k) s += hsm[r][k] * wgt[k];
        out[(size_t)(b0 + r) * NC + c] = s;
    }
}

extern "C" void kernel_launch(void* const* d_in, const int* in_sizes, int n_in,
                              void* d_out, int out_size)
{
    const float* x    = (const float*)d_in[0];
    const float* Wih0 = (const float*)d_in[1];
    const float* Wih  = (const float*)d_in[2];
    const float* Whh  = (const float*)d_in[3];
    const float* bih  = (const float*)d_in[4];
    const float* bhh  = (const float*)d_in[5];
    const float* fcW  = (const float*)d_in[6];
    const float* fcb  = (const float*)d_in[7];
    float* out = (float*)d_out;

    float *xpA, *xpB;
    cudaGetSymbolAddress((void**)&xpA, g_xpA);
    cudaGetSymbolAddress((void**)&xpB, g_xpB);

    rnn_net<<<CTAS, NT>>>(x, Wih0, Wih, Whh, bih, bhh, fcW, fcb, out, xpA, xpB);
}

// round 17
// speedup vs baseline: 1.2249x; 1.0973x over previous
#include <cuda_runtime.h>
#include <cuda_fp16.h>
#include <stdint.h>

#define B  4096
#define T  28
#define H  128
#define F0 28
#define NL 10
#define NC 10
#define BT 32           // batch rows per CTA (two m16 tiles)
#define CTAS (B / BT)   // 128 -> single wave on 148 SMs
#define NT 512          // 16 warps: 0-7 scan, 8-15 projection

// Static device buffers (no allocation allowed). xp ping-pong, fragment order.
__device__ float g_xpA[(size_t)B * T * H];
__device__ float g_xpB[(size_t)B * T * H];

// ---------------------------------------------------------------------------
// helpers
// ---------------------------------------------------------------------------
__device__ __forceinline__ uint32_t cvt_pack(float lo, float hi) {
    uint32_t r; asm("cvt.rn.f16x2.f32 %0, %1, %2;" : "=r"(r) : "f"(hi), "f"(lo));
    return r;
}
// fp32 hardware tanh (sm_75+), single MUFU op, max rel err ~2^-11
__device__ __forceinline__ float tanh32(float x) {
    float r; asm("tanh.approx.f32 %0, %1;" : "=f"(r) : "f"(x));
    return r;
}
__device__ __forceinline__ void mma16(float c[4], uint4 a, const uint32_t b[2]) {
    asm volatile("mma.sync.aligned.m16n8k16.row.col.f32.f16.f16.f32 "
        "{%0,%1,%2,%3}, {%4,%5,%6,%7}, {%8,%9}, {%0,%1,%2,%3};"
        : "+f"(c[0]), "+f"(c[1]), "+f"(c[2]), "+f"(c[3])
        : "r"(a.x), "r"(a.y), "r"(a.z), "r"(a.w), "r"(b[0]), "r"(b[1]));
}
// A-fragment word index for element (rl 0..15, kk 0..15) of one m16k16 tile
__device__ __forceinline__ int awidx(int rl, int kk) {
    int lane = ((rl & 7) << 2) | ((kk & 7) >> 1);
    int reg  = ((kk & 8) >> 2) | (rl >> 3);
    return lane * 4 + reg;               // half select = kk & 1
}

// ---------------------------------------------------------------------------
// Persistent whole-network kernel, warp-specialized, 2 m-tiles per warp:
//   scan warps (0-7):  h_t = tanh(xp_l[t] + h_{t-1} @ Whh_l^T)
//   proj warps (8-15): xp_{l+1}[t-1] = h_{t-1} @ Wih_{l+1}^T + b_{l+1}
// fp16 operands, fp32 accumulate, MUFU.TANH.F32 epilogue (precision-proven),
// streaming (.cs) hints on the once-written/once-read xp global traffic.
// ---------------------------------------------------------------------------
__global__ void __launch_bounds__(NT, 1)
rnn_net(const float* __restrict__ x,      // [B, T, F0]
        const float* __restrict__ Wih0,   // [H, F0]
        const float* __restrict__ WihR,   // [NL-1, H, H]
        const float* __restrict__ Whh,    // [NL, H, H]
        const float* __restrict__ bih,    // [NL, H]
        const float* __restrict__ bhh,    // [NL, H]
        const float* __restrict__ fcW,    // [NC, H]
        const float* __restrict__ fcb,    // [NC]
        float*       __restrict__ out,    // [B, NC]
        float*       __restrict__ xpA,
        float*       __restrict__ xpB)
{
    // h fragments: [buf][m2][kc][lane*4+reg]  (2*2*1024 words)
    __shared__ __align__(16) uint32_t AsH[4096];
    __shared__ float hsm[BT][H];

    const int tid  = threadIdx.x;
    const int lane = tid & 31;
    const int w    = tid >> 5;
    const bool scanw = (w < 8);
    const int ns   = w & 7;
    const int grp  = lane >> 2;
    const int tig  = lane & 3;
    const int b0   = blockIdx.x * BT;
    const size_t cta_off = (size_t)blockIdx.x * (T * 4096);
    float* xp0 = xpA + cta_off;
    float* xp1 = xpB + cta_off;

    // =======================================================================
    // PHASE A: xp0 = x @ Wih0^T + b_0.  Warp w -> tile (m2 = w>>3, ns).
    // =======================================================================
    {
        const int am2 = w >> 3;
        uint32_t Phi[2][2][2];
#pragma unroll
        for (int kc = 0; kc < 2; ++kc)
#pragma unroll
            for (int nt = 0; nt < 2; ++nt) {
                int n  = ns * 16 + nt * 8 + grp;
                int k0 = kc * 16 + 2 * tig;
                float v00 = (k0     < F0) ? Wih0[n * F0 + k0]     : 0.0f;
                float v01 = (k0 + 1 < F0) ? Wih0[n * F0 + k0 + 1] : 0.0f;
                float v10 = (k0 + 8 < F0) ? Wih0[n * F0 + k0 + 8] : 0.0f;
                float v11 = (k0 + 9 < F0) ? Wih0[n * F0 + k0 + 9] : 0.0f;
                Phi[kc][nt][0] = cvt_pack(v00, v01);
                Phi[kc][nt][1] = cvt_pack(v10, v11);
            }
        float bi0[2][2];
#pragma unroll
        for (int nt = 0; nt < 2; ++nt) {
            int c0 = ns * 16 + nt * 8 + 2 * tig;
            bi0[nt][0] = bih[c0]     + bhh[c0];
            bi0[nt][1] = bih[c0 + 1] + bhh[c0 + 1];
        }

        __half* AsHh = reinterpret_cast<__half*>(AsH);
        for (int t = 0; t < T; ++t) {
            for (int i = tid; i < 1024; i += NT) {
                int r = i >> 5, k = i & 31;
                float v = (k < F0)
                    ? x[((size_t)(b0 + r) * T + t) * F0 + k] : 0.0f;
                int word = (r >> 4) * 1024 + (k >> 4) * 128 + awidx(r & 15, k & 15);
                AsHh[2 * word + (k & 1)] = __float2half_rn(v);
            }
            __syncthreads();
            {
                float acc[2][4];
#pragma unroll
                for (int nt = 0; nt < 2; ++nt)
#pragma unroll
                    for (int j = 0; j < 4; ++j) acc[nt][j] = bi0[nt][j & 1];
#pragma unroll
                for (int kc = 0; kc < 2; ++kc) {
                    uint4 ah = *(const uint4*)&AsH[am2 * 1024 + kc * 128 + lane * 4];
#pragma unroll
                    for (int nt = 0; nt < 2; ++nt)
                        mma16(acc[nt], ah, Phi[kc][nt]);
                }
                float4* dst = (float4*)(xp0 + (size_t)t * 4096 + am2 * 2048 + ns * 256 + lane * 8);
                __stcs(dst,     make_float4(acc[0][0], acc[0][1], acc[0][2], acc[0][3]));
                __stcs(dst + 1, make_float4(acc[1][0], acc[1][1], acc[1][2], acc[1][3]));
            }
            __syncthreads();
        }
    }

    // =======================================================================
    // MAIN: 10 fused scan+projection layers
    // =======================================================================
    uint32_t Bw[8][2][2];   // role weight fragments (fp16)
    float bP[2][2];         // proj bias (layer l+1)

    for (int l = 0; l < NL; ++l) {
        const float* xin  = (l & 1) ? xp1 : xp0;
        float*       xout = (l & 1) ? xp0 : xp1;

        {
            const float* Wsel = scanw ? (Whh + (size_t)l * H * H)
                                      : (l < NL - 1 ? WihR + (size_t)l * H * H : nullptr);
            if (Wsel) {
#pragma unroll
                for (int kc = 0; kc < 8; ++kc)
#pragma unroll
                    for (int nt = 0; nt < 2; ++nt) {
                        int n  = ns * 16 + nt * 8 + grp;
                        int k0 = kc * 16 + 2 * tig;
                        Bw[kc][nt][0] = cvt_pack(Wsel[n * H + k0],     Wsel[n * H + k0 + 1]);
                        Bw[kc][nt][1] = cvt_pack(Wsel[n * H + k0 + 8], Wsel[n * H + k0 + 9]);
                    }
            }
            if (!scanw && l < NL - 1) {
                const float* bi = bih + (size_t)(l + 1) * H;
                const float* bh = bhh + (size_t)(l + 1) * H;
#pragma unroll
                for (int nt = 0; nt < 2; ++nt) {
                    int c0 = ns * 16 + nt * 8 + 2 * tig;
                    bP[nt][0] = bi[c0]     + bh[c0];
                    bP[nt][1] = bi[c0 + 1] + bh[c0 + 1];
                }
            }
        }

        // zero h buffer 0 (h_{-1} = 0)
        for (int i = tid; i < 2048; i += NT) AsH[i] = 0u;
        __syncthreads();

        int p = 0;
        float4 xv00, xv01, xv10, xv11;
        if (scanw) {
            const float4* s0 = (const float4*)(xin + ns * 256 + lane * 8);
            const float4* s1 = (const float4*)(xin + 2048 + ns * 256 + lane * 8);
            xv00 = __ldcs(s0); xv01 = __ldcs(s0 + 1);
            xv10 = __ldcs(s1); xv11 = __ldcs(s1 + 1);
        }

        for (int t = 0; t < T; ++t) {
            if (scanw) {
                // ---- scan: h_t = tanh(xp[t] + h_{t-1} @ Whh^T), 2 m-tiles ----
                float acc[2][2][4];     // [m2][nt][4]
                acc[0][0][0] = xv00.x; acc[0][0][1] = xv00.y; acc[0][0][2] = xv00.z; acc[0][0][3] = xv00.w;
                acc[0][1][0] = xv01.x; acc[0][1][1] = xv01.y; acc[0][1][2] = xv01.z; acc[0][1][3] = xv01.w;
                acc[1][0][0] = xv10.x; acc[1][0][1] = xv10.y; acc[1][0][2] = xv10.z; acc[1][0][3] = xv10.w;
                acc[1][1][0] = xv11.x; acc[1][1][1] = xv11.y; acc[1][1][2] = xv11.z; acc[1][1][3] = xv11.w;
                if (t + 1 < T) {
                    const float4* n0 = (const float4*)(xin + (size_t)(t + 1) * 4096 + ns * 256 + lane * 8);
                    const float4* n1 = (const float4*)(xin + (size_t)(t + 1) * 4096 + 2048 + ns * 256 + lane * 8);
                    xv00 = __ldcs(n0); xv01 = __ldcs(n0 + 1);
                    xv10 = __ldcs(n1); xv11 = __ldcs(n1 + 1);
                }
#pragma unroll
                for (int kc = 0; kc < 8; ++kc) {
                    uint4 a0 = *(const uint4*)&AsH[p * 2048 + kc * 128 + lane * 4];
                    uint4 a1 = *(const uint4*)&AsH[p * 2048 + 1024 + kc * 128 + lane * 4];
#pragma unroll
                    for (int nt = 0; nt < 2; ++nt) {
                        mma16(acc[0][nt], a0, Bw[kc][nt]);
                        mma16(acc[1][nt], a1, Bw[kc][nt]);
                    }
                }
#pragma unroll
                for (int m2 = 0; m2 < 2; ++m2) {
                    float y00 = tanh32(acc[m2][0][0]), y01 = tanh32(acc[m2][0][1]);
                    float y02 = tanh32(acc[m2][0][2]), y03 = tanh32(acc[m2][0][3]);
                    float y10 = tanh32(acc[m2][1][0]), y11 = tanh32(acc[m2][1][1]);
                    float y12 = tanh32(acc[m2][1][2]), y13 = tanh32(acc[m2][1][3]);
                    uint4 hv;
                    hv.x = cvt_pack(y00, y01);
                    hv.y = cvt_pack(y02, y03);
                    hv.z = cvt_pack(y10, y11);
                    hv.w = cvt_pack(y12, y13);
                    *(uint4*)&AsH[(1 - p) * 2048 + m2 * 1024 + ns * 128 + lane * 4] = hv;

                    if (l == NL - 1 && t == T - 1) {
#pragma unroll
                        for (int nt = 0; nt < 2; ++nt) {
                            int c0 = ns * 16 + nt * 8 + 2 * tig;
                            float a  = (nt == 0) ? y00 : y10;
                            float bb = (nt == 0) ? y01 : y11;
                            float cc = (nt == 0) ? y02 : y12;
                            float dd = (nt == 0) ? y03 : y13;
                            hsm[m2 * 16 + grp][c0]         = a;
                            hsm[m2 * 16 + grp][c0 + 1]     = bb;
                            hsm[m2 * 16 + grp + 8][c0]     = cc;
                            hsm[m2 * 16 + grp + 8][c0 + 1] = dd;
                        }
                    }
                }
            } else if (l < NL - 1 && t > 0) {
                // ---- proj: xp_{l+1}[t-1] = h_{t-1} @ Wih_{l+1}^T + b ----
                float acc[2][2][4];
#pragma unroll
                for (int m2 = 0; m2 < 2; ++m2)
#pragma unroll
                    for (int nt = 0; nt < 2; ++nt)
#pragma unroll
                        for (int j = 0; j < 4; ++j) acc[m2][nt][j] = bP[nt][j & 1];
#pragma unroll
                for (int kc = 0; kc < 8; ++kc) {
                    uint4 a0 = *(const uint4*)&AsH[p * 2048 + kc * 128 + lane * 4];
                    uint4 a1 = *(const uint4*)&AsH[p * 2048 + 1024 + kc * 128 + lane * 4];
#pragma unroll
                    for (int nt = 0; nt < 2; ++nt) {
                        mma16(acc[0][nt], a0, Bw[kc][nt]);
                        mma16(acc[1][nt], a1, Bw[kc][nt]);
                    }
                }
#pragma unroll
                for (int m2 = 0; m2 < 2; ++m2) {
                    float4* dst = (float4*)(xout + (size_t)(t - 1) * 4096 + m2 * 2048 + ns * 256 + lane * 8);
                    __stcs(dst,     make_float4(acc[m2][0][0], acc[m2][0][1], acc[m2][0][2], acc[m2][0][3]));
                    __stcs(dst + 1, make_float4(acc[m2][1][0], acc[m2][1][1], acc[m2][1][2], acc[m2][1][3]));
                }
            }
            __syncthreads();
            p ^= 1;
        }

        // tail: project h_{T-1} (in buf p)
        if (!scanw && l < NL - 1) {
            float acc[2][2][4];
#pragma unroll
            for (int m2 = 0; m2 < 2; ++m2)
#pragma unroll
                for (int nt = 0; nt < 2; ++nt)
#pragma unroll
                    for (int j = 0; j < 4; ++j) acc[m2][nt][j] = bP[nt][j & 1];
#pragma unroll
            for (int kc = 0; kc < 8; ++kc) {
                uint4 a0 = *(const uint4*)&AsH[p * 2048 + kc * 128 + lane * 4];
                uint4 a1 = *(const uint4*)&AsH[p * 2048 + 1024 + kc * 128 + lane * 4];
#pragma unroll
                for (int nt = 0; nt < 2; ++nt) {
                    mma16(acc[0][nt], a0, Bw[kc][nt]);
                    mma16(acc[1][nt], a1, Bw[kc][nt]);
                }
            }
#pragma unroll
            for (int m2 = 0; m2 < 2; ++m2) {
                float4* dst = (float4*)(xout + (size_t)(T - 1) * 4096 + m2 * 2048 + ns * 256 + lane * 8);
                __stcs(dst,     make_float4(acc[m2][0][0], acc[m2][0][1], acc[m2][0][2], acc[m2][0][3]));
                __stcs(dst + 1, make_float4(acc[m2][1][0], acc[m2][1][1], acc[m2][1][2], acc[m2][1][3]));
            }
        }
        __syncthreads();
    }

    // =======================================================================
    // FC head
    // =======================================================================
    if (tid < BT * NC) {
        int r = tid / NC, c = tid - r * NC;
        const float* wgt = fcW + c * H;
        float s = fcb[c];
#pragma unroll 8
        for (int k = 0; k < H; ++k) s += hsm[r][k] * wgt[k];
        out[(size_t)(b0 + r) * NC + c] = s;
    }
}

extern "C" void kernel_launch(void* const* d_in, const int* in_sizes, int n_in,
                              void* d_out, int out_size)
{
    const float* x    = (const float*)d_in[0];
    const float* Wih0 = (const float*)d_in[1];
    const float* Wih  = (const float*)d_in[2];
    const float* Whh  = (const float*)d_in[3];
    const float* bih  = (const float*)d_in[4];
    const float* bhh  = (const float*)d_in[5];
    const float* fcW  = (const float*)d_in[6];
    const float* fcb  = (const float*)d_in[7];
    float* out = (float*)d_out;

    float *xpA, *xpB;
    cudaGetSymbolAddress((void**)&xpA, g_xpA);
    cudaGetSymbolAddress((void**)&xpB, g_xpB);

    rnn_net<<<CTAS, NT>>>(x, Wih0, Wih, Whh, bih, bhh, fcW, fcb, out, xpA, xpB);
}